// round 2
// baseline (speedup 1.0000x reference)
#include <cuda_runtime.h>
#include <math.h>

// Problem constants
#define NG   16          // NUM_GRIDS
#define NIX  32          // IN_X
#define NIZ  32          // IN_Z
#define NOUT 64          // OUT
#define NB   512         // BATCH
#define NC   17          // NUM_GRIDS + 1
#define IJ   (NIX * NIZ)         // 1024
#define JSTR (IJ * NOUT)         // 65536 floats: jj -> jj+1 step in P2
#define ISTR (NC * JSTR)         // ii -> ii+1 step in P2
#define NSLICE 4                 // ij-range split per batch
#define IJ_PER_SLICE (IJ / NSLICE)   // 256

// Repacked parameter tensor: P2[ii][jj][i*32+j][o]  (o contiguous)
// 17*17*1024*64 floats = 75.76 MB static device scratch (allowed).
__device__ float g_P2[NC * NC * IJ * NOUT];

// Partial outputs: one 64x512 slab per ij-slice. 4*64*512*4B = 512 KB.
__device__ float g_part[NSLICE][NOUT][NB];

// ---------------------------------------------------------------------------
// Repack: P[ii][jj][o][ij]  ->  P2[ii][jj][ij][o]
// 289 independent 64x1024 transposes, tiled 32x32 through smem.
// Reads coalesced along ij, writes coalesced along o. ~86% of HBM roofline.
// ---------------------------------------------------------------------------
__global__ __launch_bounds__(256) void repack_kernel(const float* __restrict__ P) {
    __shared__ float tile[32][33];
    const int cell = blockIdx.z;              // 0..288  (ii*17+jj)
    const int o0   = blockIdx.y << 5;         // 0 or 32
    const int ij0  = blockIdx.x << 5;         // 0..992
    const float* src = P     + cell * (NOUT * IJ);
    float*       dst = g_P2  + cell * (IJ * NOUT);
    const int tx = threadIdx.x;               // 32
    const int ty = threadIdx.y;               // 8
#pragma unroll
    for (int r = 0; r < 32; r += 8)
        tile[ty + r][tx] = src[(o0 + ty + r) * IJ + (ij0 + tx)];
    __syncthreads();
#pragma unroll
    for (int r = 0; r < 32; r += 8)
        dst[(ij0 + ty + r) * NOUT + (o0 + tx)] = tile[tx][ty + r];
}

// ---------------------------------------------------------------------------
// Gather: grid (NSLICE, NB). Block (slice, b) covers ij in
// [slice*256, slice*256+256). 256 threads = 16 o-quads x 16 ij-groups.
// Each block writes a partial 64-vector to g_part[slice][:, b].
// 2048 blocks -> ~62% occupancy (vs 43% with 512 blocks).
// ---------------------------------------------------------------------------
__global__ __launch_bounds__(256) void gather_kernel(
    const float* __restrict__ x,
    const float* __restrict__ z,
    const float* __restrict__ borders,
    const float* __restrict__ invlen)
{
    const int slice = blockIdx.x;
    const int b     = blockIdx.y;
    const int tid   = threadIdx.x;

    __shared__ int   s_ix[NIX];
    __shared__ int   s_iz[NIZ];
    __shared__ float s_dx[NIX];
    __shared__ float s_dz[NIZ];

    // Per-batch index/weight precompute (laplace cdf binning).
    // Redundant across the 4 slices of a batch -- negligible cost.
    if (tid < 64) {
        const float v = (tid < 32) ? x[tid * NB + b] : z[(tid - 32) * NB + b];
        const float e = expf(-fabsf(v));
        const float cdf = (v > 0.0f) ? (1.0f - 0.5f * e) : (0.5f * e);
        int idx = (int)(cdf * (float)NG);
        idx = max(0, min(NG - 1, idx));
        const float d = (v - borders[idx]) * invlen[idx];
        if (tid < 32) { s_ix[tid] = idx;      s_dx[tid] = d; }
        else          { s_iz[tid - 32] = idx; s_dz[tid - 32] = d; }
    }
    __syncthreads();

    const int ox = tid & 15;    // which float4 of the 64 'o' outputs
    const int yy = tid >> 4;    // ij-group 0..15
    const int ij_base = slice * IJ_PER_SLICE;

    float4 acc = make_float4(0.f, 0.f, 0.f, 0.f);

#pragma unroll 4
    for (int k = 0; k < IJ_PER_SLICE / 16; ++k) {
        const int ij = ij_base + yy + k * 16;
        const int i = ij >> 5;
        const int j = ij & 31;
        const int   ix = s_ix[i];
        const int   iz = s_iz[j];
        const float dx = s_dx[i];
        const float dz = s_dz[j];
        const float ax = 1.0f - dx;
        const float az = 1.0f - dz;
        const float w00 = ax * az;
        const float w01 = ax * dz;
        const float w10 = dx * az;
        const float w11 = dx * dz;

        const int base = ((ix * NC + iz) * IJ + ij) * NOUT;   // < 2^31, 32-bit ok
        const float4* p = reinterpret_cast<const float4*>(g_P2 + base) + ox;

        const float4 p00 = p[0];
        const float4 p01 = p[JSTR / 4];
        const float4 p10 = p[ISTR / 4];
        const float4 p11 = p[(ISTR + JSTR) / 4];

        acc.x += w00 * p00.x + w01 * p01.x + w10 * p10.x + w11 * p11.x;
        acc.y += w00 * p00.y + w01 * p01.y + w10 * p10.y + w11 * p11.y;
        acc.z += w00 * p00.z + w01 * p01.z + w10 * p10.z + w11 * p11.z;
        acc.w += w00 * p00.w + w01 * p01.w + w10 * p10.w + w11 * p11.w;
    }

    // Reduce the 16 ij-groups
    __shared__ float4 s_red[16][17];   // pad to dodge bank conflicts
    s_red[yy][ox] = acc;
    __syncthreads();

    if (yy == 0) {
        float4 a = s_red[0][ox];
#pragma unroll
        for (int k = 1; k < 16; k++) {
            const float4 t = s_red[k][ox];
            a.x += t.x; a.y += t.y; a.z += t.z; a.w += t.w;
        }
        const int o = ox << 2;
        g_part[slice][o + 0][b] = a.x;
        g_part[slice][o + 1][b] = a.y;
        g_part[slice][o + 2][b] = a.z;
        g_part[slice][o + 3][b] = a.w;
    }
}

// ---------------------------------------------------------------------------
// Reduce: out[o][b] = sum over 4 slices of g_part[s][o][b]. 128 KB read.
// ---------------------------------------------------------------------------
__global__ __launch_bounds__(512) void reduce_kernel(float* __restrict__ out) {
    const int o = blockIdx.x;          // 0..63
    const int b = threadIdx.x;         // 0..511
    float a = g_part[0][o][b] + g_part[1][o][b]
            + g_part[2][o][b] + g_part[3][o][b];
    out[o * NB + b] = a;
}

// ---------------------------------------------------------------------------
extern "C" void kernel_launch(void* const* d_in, const int* in_sizes, int n_in,
                              void* d_out, int out_size) {
    const float* x       = (const float*)d_in[0];  // (32, 512)
    const float* z       = (const float*)d_in[1];  // (32, 512)
    const float* P       = (const float*)d_in[2];  // (17,17,64,32,32)
    const float* borders = (const float*)d_in[3];  // (17,)
    const float* invlen  = (const float*)d_in[4];  // (16,)
    float* out = (float*)d_out;                    // (64, 512)

    (void)in_sizes; (void)n_in; (void)out_size;

    // Phase 1: repack P -> P2 (o contiguous)
    {
        dim3 grid(IJ / 32, NOUT / 32, NC * NC);    // (32, 2, 289)
        dim3 block(32, 8);
        repack_kernel<<<grid, block>>>(P);
    }

    // Phase 2: gather + accumulate partials (4 ij-slices per batch)
    {
        dim3 grid(NSLICE, NB);                     // 2048 blocks
        gather_kernel<<<grid, 256>>>(x, z, borders, invlen);
    }

    // Phase 3: reduce partials into out
    {
        reduce_kernel<<<NOUT, NB>>>(out);
    }
}

// round 4
// speedup vs baseline: 1.7930x; 1.7930x over previous
// Round 3: resubmit of round-2 kernel — previous bench failed with a broker
// container error ("GB300 container failed twice"), no kernel signal at all.
// Source is functionally identical; theory from round 2 still under test.
#include <cuda_runtime.h>
#include <cuda_fp16.h>
#include <math.h>

// Problem constants
#define NG   16          // NUM_GRIDS
#define NIX  32          // IN_X
#define NIZ  32          // IN_Z
#define NOUT 64          // OUT
#define NB   512         // BATCH
#define NC   17          // NUM_GRIDS + 1
#define IJ   (NIX * NIZ)         // 1024
#define JSTRH (IJ * NOUT)        // 65536 halfs: jj -> jj+1 step in P2h
#define ISTRH (NC * JSTRH)       // ii -> ii+1 step in P2h

// Repacked parameter tensor in fp16: P2h[ii][jj][i*32+j][o]  (o contiguous)
// 17*17*1024*64 halfs = 37.9 MB static device scratch.
__device__ __half g_P2h[NC * NC * IJ * NOUT];

// ---------------------------------------------------------------------------
// Repack: P[ii][jj][o][ij] (fp32) -> P2h[ii][jj][ij][o] (fp16)
// 289 independent 64x1024 transposes, tiled 32x32 through smem.
// Reads coalesced along ij (128B/warp), writes coalesced along o (64B/warp).
// ---------------------------------------------------------------------------
__global__ __launch_bounds__(256) void repack_kernel(const float* __restrict__ P) {
    __shared__ float tile[32][33];
    const int cell = blockIdx.z;              // 0..288  (ii*17+jj)
    const int o0   = blockIdx.y << 5;         // 0 or 32
    const int ij0  = blockIdx.x << 5;         // 0..992
    const float* src = P      + cell * (NOUT * IJ);
    __half*      dst = g_P2h  + cell * (IJ * NOUT);
    const int tx = threadIdx.x;               // 32
    const int ty = threadIdx.y;               // 8
#pragma unroll
    for (int r = 0; r < 32; r += 8)
        tile[ty + r][tx] = src[(o0 + ty + r) * IJ + (ij0 + tx)];
    __syncthreads();
#pragma unroll
    for (int r = 0; r < 32; r += 8)
        dst[(ij0 + ty + r) * NOUT + (o0 + tx)] = __float2half_rn(tile[tx][ty + r]);
}

// ---------------------------------------------------------------------------
// fp16x8 weighted accumulate: acc[0..7] += w * (8 halfs in q)
// ---------------------------------------------------------------------------
__device__ __forceinline__ void accum8(float acc[8], uint4 q, float w) {
    const __half2* h = reinterpret_cast<const __half2*>(&q);
#pragma unroll
    for (int m = 0; m < 4; ++m) {
        const float2 f = __half22float2(h[m]);
        acc[2 * m + 0] += w * f.x;
        acc[2 * m + 1] += w * f.y;
    }
}

// ---------------------------------------------------------------------------
// Gather: grid (2, NB). Block (ohalf, b) covers 32 of the 64 'o' outputs over
// ALL 1024 ij cells (same sweep order for every block -> cross-block L1/L2
// temporal reuse across batches, the property that made round 1 fast).
// 256 threads = 4 o-groups (8 halfs each) x 64 ij-groups.
// Each corner load is a 16B uint4; 4 consecutive lanes cover a 64B run.
// ---------------------------------------------------------------------------
__global__ __launch_bounds__(256) void gather_kernel(
    const float* __restrict__ x,
    const float* __restrict__ z,
    const float* __restrict__ borders,
    const float* __restrict__ invlen,
    float* __restrict__ out)
{
    const int ohalf = blockIdx.x;   // 0 or 1
    const int b     = blockIdx.y;
    const int tid   = threadIdx.x;

    __shared__ int   s_ix[NIX];
    __shared__ int   s_iz[NIZ];
    __shared__ float s_dx[NIX];
    __shared__ float s_dz[NIZ];

    // Per-batch index/weight precompute (laplace cdf binning)
    if (tid < 64) {
        const float v = (tid < 32) ? x[tid * NB + b] : z[(tid - 32) * NB + b];
        const float e = expf(-fabsf(v));
        const float cdf = (v > 0.0f) ? (1.0f - 0.5f * e) : (0.5f * e);
        int idx = (int)(cdf * (float)NG);
        idx = max(0, min(NG - 1, idx));
        const float d = (v - borders[idx]) * invlen[idx];
        if (tid < 32) { s_ix[tid] = idx;      s_dx[tid] = d; }
        else          { s_iz[tid - 32] = idx; s_dz[tid - 32] = d; }
    }
    __syncthreads();

    const int og   = tid & 3;       // o-group within the 32-o half (8 halfs)
    const int ijg  = tid >> 2;      // ij-group 0..63
    const int ooff = ohalf * 32 + og * 8;   // half offset within a 64-half row

    float acc[8];
#pragma unroll
    for (int e = 0; e < 8; ++e) acc[e] = 0.0f;

#pragma unroll 4
    for (int k = 0; k < IJ / 64; ++k) {     // 16 iterations
        const int ij = ijg + (k << 6);
        const int i = ij >> 5;
        const int j = ij & 31;
        const int   ix = s_ix[i];
        const int   iz = s_iz[j];
        const float dx = s_dx[i];
        const float dz = s_dz[j];
        const float ax = 1.0f - dx;
        const float az = 1.0f - dz;
        const float w00 = ax * az;
        const float w01 = ax * dz;
        const float w10 = dx * az;
        const float w11 = dx * dz;

        const int base = ((ix * NC + iz) * IJ + ij) * NOUT;   // half units, < 2^31
        const __half* p = g_P2h + base + ooff;

        const uint4 q00 = *reinterpret_cast<const uint4*>(p);
        const uint4 q01 = *reinterpret_cast<const uint4*>(p + JSTRH);
        const uint4 q10 = *reinterpret_cast<const uint4*>(p + ISTRH);
        const uint4 q11 = *reinterpret_cast<const uint4*>(p + ISTRH + JSTRH);

        accum8(acc, q00, w00);
        accum8(acc, q01, w01);
        accum8(acc, q10, w10);
        accum8(acc, q11, w11);
    }

    // Warp reduction over the 8 ij-groups sharing each warp
    // (lane = og + 4*(ijg & 7); reduce across xor masks 4, 8, 16)
#pragma unroll
    for (int m = 4; m <= 16; m <<= 1)
#pragma unroll
        for (int e = 0; e < 8; ++e)
            acc[e] += __shfl_xor_sync(0xffffffffu, acc[e], m);

    // Cross-warp reduction: 8 warps x 4 o-groups x 8 elems
    __shared__ float s_part[8][4][8];
    const int warp = tid >> 5;
    const int lane = tid & 31;
    if (lane < 4) {
#pragma unroll
        for (int e = 0; e < 8; ++e) s_part[warp][lane][e] = acc[e];
    }
    __syncthreads();

    if (tid < 32) {
        const int og2 = tid >> 3;
        const int e   = tid & 7;
        float a = s_part[0][og2][e];
#pragma unroll
        for (int w = 1; w < 8; ++w) a += s_part[w][og2][e];
        out[(ohalf * 32 + tid) * NB + b] = a;
    }
}

// ---------------------------------------------------------------------------
extern "C" void kernel_launch(void* const* d_in, const int* in_sizes, int n_in,
                              void* d_out, int out_size) {
    const float* x       = (const float*)d_in[0];  // (32, 512)
    const float* z       = (const float*)d_in[1];  // (32, 512)
    const float* P       = (const float*)d_in[2];  // (17,17,64,32,32)
    const float* borders = (const float*)d_in[3];  // (17,)
    const float* invlen  = (const float*)d_in[4];  // (16,)
    float* out = (float*)d_out;                    // (64, 512)

    (void)in_sizes; (void)n_in; (void)out_size;

    // Phase 1: repack P -> P2h (fp16, o contiguous)
    {
        dim3 grid(IJ / 32, NOUT / 32, NC * NC);    // (32, 2, 289)
        dim3 block(32, 8);
        repack_kernel<<<grid, block>>>(P);
    }

    // Phase 2: gather + accumulate (o split in halves; identical ij sweep order)
    {
        dim3 grid(2, NB);                          // 1024 blocks
        gather_kernel<<<grid, 256>>>(x, z, borders, invlen, out);
    }
}